// round 15
// baseline (speedup 1.0000x reference)
#include <cuda_runtime.h>
#include <cstdint>

#define TOPK     20
#define ROW      32000
#define NROWS    4096
#define TOT_F4   32768000       // 4096 * 8000 float4 elements
#define DIM      1024
#define NB       4
#define NPROTO   64
#define NCHUNK   128            // pool chunks (8 tokens each)
#define CAPC     192            // per-row candidate capacity
#define THR0     2.75f          // gather threshold (top-20 quantile ~3.23)
#define THR_HI   3.0f           // patch refine threshold (E[c_hi]~43)
#define SUBC     64             // refined subset capacity
#define C1B      6              // float4 loads in flight per thread
#define CTA_F4   (256 * C1B * 4)    // 6144 float4 per CTA (96KB)
#define FULLM    0xFFFFFFFFu

// -------- device scratch (static __device__, no allocations) --------
__device__ __align__(16) float g_part[NB * NCHUNK * DIM];  // 2 MB
__device__ int                g_flag[NB];
__device__ int                g_ccnt[NROWS];
__device__ unsigned long long g_cand[NROWS * CAPC];        // ~6 MB

// =======================================================================
// helpers
// =======================================================================
__device__ __forceinline__ unsigned long long umax64(unsigned long long a,
                                                     unsigned long long b) {
    return a > b ? a : b;
}
__device__ __forceinline__ unsigned long long make_key(float v, int col) {
    unsigned u   = __float_as_uint(v);
    unsigned sbl = (u & 0x80000000u) ? ~u : (u | 0x80000000u);
    return ((unsigned long long)sbl << 32) |
           (unsigned long long)(0xFFFFFFFFu - (unsigned)col);
}

// =======================================================================
// K1: token-chunk partial sums of hidden (512 blocks x 256 thr, MLP=8)
//     also zeroes per-row candidate counters for this replay
// =======================================================================
__global__ __launch_bounds__(256, 4)
void pool_kernel(const float* __restrict__ hidden) {
    int blk = blockIdx.x;
    int b   = blk >> 7;                 // /128
    int c   = blk & 127;
    int d4  = threadIdx.x;              // 0..255 float4 columns

    const float4* p = (const float4*)(hidden
                    + (size_t)b * (1024 * DIM) + (size_t)c * 8 * DIM) + d4;
    float4 r[8];
    #pragma unroll
    for (int t = 0; t < 8; ++t) r[t] = p[t * 256];
    float4 s = r[0];
    #pragma unroll
    for (int t = 1; t < 8; ++t) {
        s.x += r[t].x; s.y += r[t].y; s.z += r[t].z; s.w += r[t].w;
    }
    ((float4*)g_part)[(size_t)(b * NCHUNK + c) * 256 + d4] = s;

    if (blk < 16) g_ccnt[blk * 256 + threadIdx.x] = 0;
}

// =======================================================================
// K2: flag[b] = sign( sum_p (emb . proto_p)/max(||proto_p||,eps) ) > 0
//     (positive common factors 1/64 and 1/||emb|| dropped)
// =======================================================================
__global__ void flag_kernel(const float* __restrict__ proto) {
    __shared__ float s_emb[DIM];
    __shared__ float s_sim[32];
    int b    = blockIdx.x;
    int tid  = threadIdx.x;
    int w    = tid >> 5;
    int lane = tid & 31;

    float e = 0.f;
    #pragma unroll 8
    for (int c = 0; c < NCHUNK; ++c) e += g_part[(b * NCHUNK + c) * DIM + tid];
    s_emb[tid] = e;
    __syncthreads();

    float acc = 0.f;
    for (int p = w; p < NPROTO; p += 32) {
        float sq = 0.f, dt = 0.f;
        for (int d = lane; d < DIM; d += 32) {
            float x = proto[p * DIM + d];
            sq += x * x;
            dt += x * s_emb[d];
        }
        #pragma unroll
        for (int o = 16; o; o >>= 1) {
            sq += __shfl_xor_sync(FULLM, sq, o);
            dt += __shfl_xor_sync(FULLM, dt, o);
        }
        acc += dt / fmaxf(sqrtf(sq), 1e-8f);
    }
    if (lane == 0) s_sim[w] = acc;
    __syncthreads();
    if (tid == 0) {
        float t = 0.f;
        #pragma unroll
        for (int i = 0; i < 32; ++i) t += s_sim[i];
        g_flag[b] = (t > 0.f) ? 1 : 0;
    }
}

// =======================================================================
// K3: PURE blocked streaming copy + candidate gather (no epilogue)
// =======================================================================
__global__ __launch_bounds__(256, 6)
void copy_kernel(const float* __restrict__ logits, float* __restrict__ out) {
    const float4* __restrict__ src4 = (const float4*)logits;
    float4*       __restrict__ dst4 = (float4*)out;
    int tid  = threadIdx.x;
    int base = blockIdx.x * CTA_F4;

    #pragma unroll
    for (int it = 0; it < 4; ++it) {
        int b0 = base + it * (256 * C1B) + tid;
        float4 r[C1B];
        #pragma unroll
        for (int k = 0; k < C1B; ++k) {
            int ix = b0 + k * 256;
            r[k] = (ix < TOT_F4) ? __ldcs(&src4[ix])
                                 : make_float4(0.f, 0.f, 0.f, 0.f);
        }
        #pragma unroll
        for (int k = 0; k < C1B; ++k) {
            int ix = b0 + k * 256;
            if (ix < TOT_F4) __stcs(&dst4[ix], r[k]);
        }
        #pragma unroll
        for (int k = 0; k < C1B; ++k) {
            int ix = b0 + k * 256;
            if (ix < TOT_F4) {
                float mx = fmaxf(fmaxf(r[k].x, r[k].y), fmaxf(r[k].z, r[k].w));
                if (mx > THR0) {
                    float vv[4] = {r[k].x, r[k].y, r[k].z, r[k].w};
                    #pragma unroll
                    for (int c = 0; c < 4; ++c) {
                        if (vv[c] > THR0) {
                            int g   = ix * 4 + c;
                            int row = g / ROW;
                            int col = g - row * ROW;
                            int slot = atomicAdd(&g_ccnt[row], 1);
                            if (slot < CAPC)
                                g_cand[row * CAPC + slot] = make_key(vv[c], col);
                        }
                    }
                }
            }
        }
    }
}

// =======================================================================
// K4: warp-synchronous two-level rank-count patch, 1 warp per row
//     (ballot compaction, no shared atomics, no block barriers)
// =======================================================================
__global__ __launch_bounds__(256, 8)
void patch_kernel(const float* __restrict__ logits, float* __restrict__ out) {
    __shared__ __align__(16) unsigned long long s_sub[8][SUBC];   // 4 KB
    int w    = threadIdx.x >> 5;
    int lane = threadIdx.x & 31;
    int row  = blockIdx.x * 8 + w;
    int b    = row >> 10;

    if (!g_flag[b]) return;
    int cnt = g_ccnt[row];
    float* dst = out + (size_t)row * ROW;

    if (cnt >= TOPK && cnt <= CAPC) {
        const unsigned long long KHI =
            make_key(THR_HI, 0) & 0xFFFFFFFF00000000ULL;
        const unsigned long long* cp = g_cand + (size_t)row * CAPC;

        // ---- load 6 keys/lane + ballot-compact survivors into s_sub ----
        unsigned long long k[6];
        int cbase = 0;
        #pragma unroll
        for (int j = 0; j < 6; ++j) {
            int i = lane + j * 32;
            unsigned long long kk = (i < cnt) ? cp[i] : 0ULL;
            k[j] = kk;
            bool pred = kk > KHI;
            unsigned m  = __ballot_sync(FULLM, pred);
            int pos = cbase + __popc(m & ((1u << lane) - 1u));
            if (pred && pos < SUBC) s_sub[w][pos] = kk;
            cbase += __popc(m);
        }
        int c_hi = cbase;                // uniform across warp
        __syncwarp();

        if (c_hi >= TOPK && c_hi <= SUBC) {
            // ---- level 2: rank count over ~43 refined keys ----
            const unsigned long long* sb = s_sub[w];
            unsigned long long my0 = (lane < c_hi)      ? sb[lane]      : 0ULL;
            unsigned long long my1 = (lane + 32 < c_hi) ? sb[lane + 32] : 0ULL;
            int r0 = 0, r1 = 0;
            #pragma unroll 4
            for (int i = 0; i < c_hi; ++i) {
                unsigned long long ki = sb[i];
                r0 += (ki > my0);
                r1 += (ki > my1);
            }
            if (lane < c_hi && r0 < TOPK) {
                unsigned col = 0xFFFFFFFFu - (unsigned)my0;
                if (col < ROW) dst[col] = -100.0f;
            }
            if (lane + 32 < c_hi && r1 < TOPK) {
                unsigned col = 0xFFFFFFFFu - (unsigned)my1;
                if (col < ROW) dst[col] = -100.0f;
            }
        } else {
            // ---- level-1 fallback (rare): shfl-broadcast rank over cnt ----
            int rk[6] = {0, 0, 0, 0, 0, 0};
            #pragma unroll 1
            for (int j2 = 0; j2 < 6; ++j2) {
                for (int sl = 0; sl < 32; ++sl) {
                    unsigned long long ki = __shfl_sync(FULLM, k[j2], sl);
                    int gi = sl + j2 * 32;
                    if (gi < cnt) {
                        #pragma unroll
                        for (int j = 0; j < 6; ++j) rk[j] += (ki > k[j]);
                    }
                }
            }
            #pragma unroll
            for (int j = 0; j < 6; ++j) {
                int i = lane + j * 32;
                if (i < cnt && rk[j] < TOPK) {
                    unsigned col = 0xFFFFFFFFu - (unsigned)k[j];
                    if (col < ROW) dst[col] = -100.0f;
                }
            }
        }
    } else {
        // ---- deterministic slow path (statistically never taken) ----
        const float* srcr = logits + (size_t)row * ROW;
        unsigned long long prev = ~0ULL;
        for (int t = 0; t < TOPK; ++t) {
            unsigned long long best = 0ULL;
            for (int i = lane; i < ROW; i += 32) {
                unsigned long long key = make_key(srcr[i], i);
                if (key < prev) best = umax64(best, key);
            }
            #pragma unroll
            for (int o = 16; o; o >>= 1)
                best = umax64(best, __shfl_xor_sync(FULLM, best, o));
            prev = best;
            unsigned col = 0xFFFFFFFFu - (unsigned)best;
            if (lane == 0 && best != 0ULL && col < ROW)
                dst[col] = -100.0f;
        }
    }
}

// =======================================================================
extern "C" void kernel_launch(void* const* d_in, const int* in_sizes, int n_in,
                              void* d_out, int out_size) {
    const float* proto  = (const float*)d_in[0];  // [64, 1024]
    const float* hidden = (const float*)d_in[1];  // [4, 1024, 1024]
    const float* logits = (const float*)d_in[2];  // [4, 1, 1024, 32000]
    float* out = (float*)d_out;

    pool_kernel<<<NB * NCHUNK, 256>>>(hidden);
    flag_kernel<<<NB, 1024>>>(proto);
    int grid_copy = (TOT_F4 + CTA_F4 - 1) / CTA_F4;   // 5334
    copy_kernel<<<grid_copy, 256>>>(logits, out);
    patch_kernel<<<NROWS / 8, 256>>>(logits, out);
}

// round 16
// speedup vs baseline: 1.0502x; 1.0502x over previous
#include <cuda_runtime.h>
#include <cstdint>

#define TOPK     20
#define ROW      32000
#define NROWS    4096
#define TOT_F4   32768000       // 4096 * 8000 float4 elements
#define DIM      1024
#define NB       4
#define NPROTO   64
#define NCHUNK   128            // pool chunks (8 tokens each)
#define CAPC     192            // per-row candidate capacity
#define THR0     2.75f          // gather threshold (top-20 quantile ~3.23)
#define THR_HI   3.0f           // patch refine threshold (E[c_hi]~43)
#define SUBC     64             // refined subset capacity
#define C1B      6              // float4 loads in flight per thread
#define CTA_F4   (256 * C1B * 4)    // 6144 float4 per CTA (96KB)
#define FULLM    0xFFFFFFFFu

// -------- device scratch (static __device__, no allocations) --------
__device__ __align__(16) float g_part[NB * NCHUNK * DIM];  // 2 MB
__device__ int                g_flag[NB];
__device__ int                g_ccnt[NROWS];
__device__ unsigned long long g_cand[NROWS * CAPC];        // ~6 MB

// =======================================================================
// helpers
// =======================================================================
__device__ __forceinline__ unsigned long long umax64(unsigned long long a,
                                                     unsigned long long b) {
    return a > b ? a : b;
}
__device__ __forceinline__ unsigned long long make_key(float v, int col) {
    unsigned u   = __float_as_uint(v);
    unsigned sbl = (u & 0x80000000u) ? ~u : (u | 0x80000000u);
    return ((unsigned long long)sbl << 32) |
           (unsigned long long)(0xFFFFFFFFu - (unsigned)col);
}

// =======================================================================
// K1: token-chunk partial sums of hidden (512 blocks x 256 thr, MLP=8)
//     also zeroes per-row candidate counters for this replay
// =======================================================================
__global__ __launch_bounds__(256, 4)
void pool_kernel(const float* __restrict__ hidden) {
    int blk = blockIdx.x;
    int b   = blk >> 7;                 // /128
    int c   = blk & 127;
    int d4  = threadIdx.x;              // 0..255 float4 columns

    const float4* p = (const float4*)(hidden
                    + (size_t)b * (1024 * DIM) + (size_t)c * 8 * DIM) + d4;
    float4 r[8];
    #pragma unroll
    for (int t = 0; t < 8; ++t) r[t] = p[t * 256];
    float4 s = r[0];
    #pragma unroll
    for (int t = 1; t < 8; ++t) {
        s.x += r[t].x; s.y += r[t].y; s.z += r[t].z; s.w += r[t].w;
    }
    ((float4*)g_part)[(size_t)(b * NCHUNK + c) * 256 + d4] = s;

    if (blk < 16) g_ccnt[blk * 256 + threadIdx.x] = 0;
}

// =======================================================================
// K2: flag[b] = sign( sum_p (emb . proto_p)/max(||proto_p||,eps) ) > 0
//     (positive common factors 1/64 and 1/||emb|| dropped)
// =======================================================================
__global__ void flag_kernel(const float* __restrict__ proto) {
    __shared__ float s_emb[DIM];
    __shared__ float s_sim[32];
    int b    = blockIdx.x;
    int tid  = threadIdx.x;
    int w    = tid >> 5;
    int lane = tid & 31;

    float e = 0.f;
    #pragma unroll 8
    for (int c = 0; c < NCHUNK; ++c) e += g_part[(b * NCHUNK + c) * DIM + tid];
    s_emb[tid] = e;
    __syncthreads();

    float acc = 0.f;
    for (int p = w; p < NPROTO; p += 32) {
        float sq = 0.f, dt = 0.f;
        for (int d = lane; d < DIM; d += 32) {
            float x = proto[p * DIM + d];
            sq += x * x;
            dt += x * s_emb[d];
        }
        #pragma unroll
        for (int o = 16; o; o >>= 1) {
            sq += __shfl_xor_sync(FULLM, sq, o);
            dt += __shfl_xor_sync(FULLM, dt, o);
        }
        acc += dt / fmaxf(sqrtf(sq), 1e-8f);
    }
    if (lane == 0) s_sim[w] = acc;
    __syncthreads();
    if (tid == 0) {
        float t = 0.f;
        #pragma unroll
        for (int i = 0; i < 32; ++i) t += s_sim[i];
        g_flag[b] = (t > 0.f) ? 1 : 0;
    }
}

// =======================================================================
// K3: PURE blocked streaming copy + candidate gather (no epilogue)
// =======================================================================
__global__ __launch_bounds__(256, 6)
void copy_kernel(const float* __restrict__ logits, float* __restrict__ out) {
    const float4* __restrict__ src4 = (const float4*)logits;
    float4*       __restrict__ dst4 = (float4*)out;
    int tid  = threadIdx.x;
    int base = blockIdx.x * CTA_F4;

    #pragma unroll
    for (int it = 0; it < 4; ++it) {
        int b0 = base + it * (256 * C1B) + tid;
        float4 r[C1B];
        #pragma unroll
        for (int k = 0; k < C1B; ++k) {
            int ix = b0 + k * 256;
            r[k] = (ix < TOT_F4) ? __ldcs(&src4[ix])
                                 : make_float4(0.f, 0.f, 0.f, 0.f);
        }
        #pragma unroll
        for (int k = 0; k < C1B; ++k) {
            int ix = b0 + k * 256;
            if (ix < TOT_F4) __stcs(&dst4[ix], r[k]);
        }
        #pragma unroll
        for (int k = 0; k < C1B; ++k) {
            int ix = b0 + k * 256;
            if (ix < TOT_F4) {
                float mx = fmaxf(fmaxf(r[k].x, r[k].y), fmaxf(r[k].z, r[k].w));
                if (mx > THR0) {
                    float vv[4] = {r[k].x, r[k].y, r[k].z, r[k].w};
                    #pragma unroll
                    for (int c = 0; c < 4; ++c) {
                        if (vv[c] > THR0) {
                            int g   = ix * 4 + c;
                            int row = g / ROW;
                            int col = g - row * ROW;
                            int slot = atomicAdd(&g_ccnt[row], 1);
                            if (slot < CAPC)
                                g_cand[row * CAPC + slot] = make_key(vv[c], col);
                        }
                    }
                }
            }
        }
    }
}

// =======================================================================
// K4: two-level rank-count patch, 4 warps (128 thr) per row, 2 rows/CTA
//     grid 2048 (16384 warps) — latency-bound, so maximize warp count
// =======================================================================
__global__ __launch_bounds__(256, 8)
void patch_kernel(const float* __restrict__ logits, float* __restrict__ out) {
    __shared__ __align__(16) unsigned long long s_keys[2][CAPC];  // 3 KB
    __shared__ __align__(16) unsigned long long s_sub[2][SUBC];   // 1 KB
    __shared__ int s_c[2];
    int rloc = threadIdx.x >> 7;        // 0..1 row within block
    int t128 = threadIdx.x & 127;       // 0..127 thread within row group
    int row  = blockIdx.x * 2 + rloc;
    int b    = row >> 10;

    int fl  = g_flag[b];
    int cnt = g_ccnt[row];
    bool fast = fl && (cnt >= TOPK) && (cnt <= CAPC);

    if (t128 == 0) s_c[rloc] = 0;
    __syncthreads();

    // ---- stage + hi-filter: 128 threads x up to 2 keys (coalesced) ----
    const unsigned long long KHI =
        make_key(THR_HI, 0) & 0xFFFFFFFF00000000ULL;
    unsigned long long mk[2] = {0ULL, 0ULL};
    if (fast) {
        const unsigned long long* cp = g_cand + (size_t)row * CAPC;
        #pragma unroll
        for (int j = 0; j < 2; ++j) {
            int i = t128 + j * 128;
            unsigned long long k = (i < cnt && i < CAPC) ? cp[i] : 0ULL;
            mk[j] = k;
            if (i < CAPC) s_keys[rloc][i] = k;
            if (k > KHI) {
                int slot = atomicAdd(&s_c[rloc], 1);
                if (slot < SUBC) s_sub[rloc][slot] = k;
            }
        }
    }
    __syncthreads();
    if (!fl) return;

    float* dst = out + (size_t)row * ROW;
    int c_hi = s_c[rloc];

    if (fast && c_hi >= TOPK && c_hi <= SUBC) {
        // ---- level 2: rank count over ~43 refined keys, 1 key/thread ----
        if (t128 < c_hi) {
            const unsigned long long* sb = s_sub[rloc];
            unsigned long long my = sb[t128];
            int rk = 0;
            #pragma unroll 4
            for (int i = 0; i < c_hi; ++i) rk += (sb[i] > my);
            if (rk < TOPK) {
                unsigned col = 0xFFFFFFFFu - (unsigned)my;
                if (col < ROW) dst[col] = -100.0f;
            }
        }
    } else if (fast) {
        // ---- level 1 fallback: rank count over all cnt keys (rare) ----
        const unsigned long long* sk = s_keys[rloc];
        unsigned long long m0 = mk[0], m1 = mk[1];
        int r0 = 0, r1 = 0;
        #pragma unroll 4
        for (int i = 0; i < cnt; ++i) {
            unsigned long long ki = sk[i];
            r0 += (ki > m0);
            r1 += (ki > m1);
        }
        int rk[2] = {r0, r1};
        #pragma unroll
        for (int j = 0; j < 2; ++j) {
            int i = t128 + j * 128;
            if (i < cnt && i < CAPC && rk[j] < TOPK) {
                unsigned col = 0xFFFFFFFFu - (unsigned)mk[j];
                if (col < ROW) dst[col] = -100.0f;
            }
        }
    } else {
        // ---- deterministic slow path (statistically never taken) ----
        if (t128 >= 32) return;
        int lane = t128;
        const float* srcr = logits + (size_t)row * ROW;
        unsigned long long prev = ~0ULL;
        for (int t = 0; t < TOPK; ++t) {
            unsigned long long best = 0ULL;
            for (int i = lane; i < ROW; i += 32) {
                unsigned long long key = make_key(srcr[i], i);
                if (key < prev) best = umax64(best, key);
            }
            #pragma unroll
            for (int o = 16; o; o >>= 1)
                best = umax64(best, __shfl_xor_sync(FULLM, best, o));
            prev = best;
            unsigned col = 0xFFFFFFFFu - (unsigned)best;
            if (lane == 0 && best != 0ULL && col < ROW)
                dst[col] = -100.0f;
        }
    }
}

// =======================================================================
extern "C" void kernel_launch(void* const* d_in, const int* in_sizes, int n_in,
                              void* d_out, int out_size) {
    const float* proto  = (const float*)d_in[0];  // [64, 1024]
    const float* hidden = (const float*)d_in[1];  // [4, 1024, 1024]
    const float* logits = (const float*)d_in[2];  // [4, 1, 1024, 32000]
    float* out = (float*)d_out;

    pool_kernel<<<NB * NCHUNK, 256>>>(hidden);
    flag_kernel<<<NB, 1024>>>(proto);
    int grid_copy = (TOT_F4 + CTA_F4 - 1) / CTA_F4;   // 5334
    copy_kernel<<<grid_copy, 256>>>(logits, out);
    patch_kernel<<<NROWS / 2, 256>>>(logits, out);
}

// round 17
// speedup vs baseline: 1.1118x; 1.0587x over previous
#include <cuda_runtime.h>
#include <cstdint>

#define TOPK     20
#define ROW      32000
#define NROWS    4096
#define TOT_F4   32768000       // 4096 * 8000 float4 elements
#define DIM      1024
#define NB       4
#define NPROTO   64
#define NCHUNK   128            // pool chunks (8 tokens each)
#define CAPC     192            // per-row candidate capacity
#define THR0     2.75f          // gather threshold (top-20 quantile ~3.23)
#define THR_HI   3.0f           // patch refine threshold (E[c_hi]~43)
#define SUBC     64             // refined subset capacity
#define C1B      6              // float4 loads in flight per thread
#define CTA_F4   (256 * C1B * 4)    // 6144 float4 per CTA (96KB)
#define NPOOL    512            // pool blocks (scheduled first)
#define NCOPY    5334           // copy blocks
#define FULLM    0xFFFFFFFFu

// -------- device scratch (zero-initialized at module load) --------
__device__ __align__(16) float g_part[NB * NCHUNK * DIM];  // 2 MB
__device__ int                g_flag[NB];
__device__ int                g_pdone[NB];
__device__ int                g_ccnt[NROWS];               // zeroed by patch each replay
__device__ unsigned long long g_cand[NROWS * CAPC];        // ~6 MB

// =======================================================================
// helpers
// =======================================================================
__device__ __forceinline__ unsigned long long umax64(unsigned long long a,
                                                     unsigned long long b) {
    return a > b ? a : b;
}
__device__ __forceinline__ unsigned long long make_key(float v, int col) {
    unsigned u   = __float_as_uint(v);
    unsigned sbl = (u & 0x80000000u) ? ~u : (u | 0x80000000u);
    return ((unsigned long long)sbl << 32) |
           (unsigned long long)(0xFFFFFFFFu - (unsigned)col);
}

// =======================================================================
// K1: heterogeneous grid — blocks [0,512): pool + hidden flag epilogue;
//     blocks [512, 5846): streaming copy + candidate gather.
//     Pool blocks finish in wave 1; the per-batch flag tail (last pool
//     CTA per batch) is hidden under the concurrent copy stream.
// =======================================================================
__global__ __launch_bounds__(256, 6)
void fused_main(const float* __restrict__ hidden,
                const float* __restrict__ proto,
                const float* __restrict__ logits,
                float* __restrict__ out) {
    __shared__ __align__(16) float s_emb[DIM];   // used by flag epilogue only
    __shared__ float s_sim[8];
    __shared__ int   s_do;

    int blk = blockIdx.x;
    int tid = threadIdx.x;

    if (blk < NPOOL) {
        // ------------------- pool body (MLP=8) -------------------
        int b  = blk >> 7;               // /128
        int c  = blk & 127;
        int d4 = tid;                    // 0..255 float4 columns

        const float4* p = (const float4*)(hidden
                        + (size_t)b * (1024 * DIM) + (size_t)c * 8 * DIM) + d4;
        float4 r[8];
        #pragma unroll
        for (int t = 0; t < 8; ++t) r[t] = p[t * 256];
        float4 s = r[0];
        #pragma unroll
        for (int t = 1; t < 8; ++t) {
            s.x += r[t].x; s.y += r[t].y; s.z += r[t].z; s.w += r[t].w;
        }
        ((float4*)g_part)[(size_t)(b * NCHUNK + c) * 256 + d4] = s;

        // ---- last pool CTA of this batch computes the flag ----
        if (tid == 0) {
            __threadfence();
            int old = atomicAdd(&g_pdone[b], 1);
            s_do = (old == NCHUNK - 1) ? 1 : 0;
        }
        __syncthreads();
        if (!s_do) return;
        __threadfence();                 // acquire all g_part writes

        {
            const float4* gp = (const float4*)g_part + (size_t)b * NCHUNK * 256 + d4;
            float4 e = make_float4(0.f, 0.f, 0.f, 0.f);
            #pragma unroll 8
            for (int cc = 0; cc < NCHUNK; ++cc) {
                float4 v = gp[cc * 256];
                e.x += v.x; e.y += v.y; e.z += v.z; e.w += v.w;
            }
            ((float4*)s_emb)[d4] = e;
        }
        __syncthreads();

        // flag[b] = sign( sum_p (emb . proto_p)/max(||proto_p||,eps) ) > 0
        // (positive common factors 1/64 and 1/||emb|| dropped)
        int w    = tid >> 5;
        int lane = tid & 31;
        float acc = 0.f;
        for (int pi = 0; pi < 8; ++pi) {
            int pr = w * 8 + pi;
            const float4* pp = (const float4*)(proto + (size_t)pr * DIM);
            float sq = 0.f, dt = 0.f;
            #pragma unroll
            for (int i = 0; i < 8; ++i) {
                int d4i = lane + i * 32;
                float4 x = pp[d4i];
                float4 e = ((const float4*)s_emb)[d4i];
                sq += x.x * x.x + x.y * x.y + x.z * x.z + x.w * x.w;
                dt += x.x * e.x + x.y * e.y + x.z * e.z + x.w * e.w;
            }
            #pragma unroll
            for (int o = 16; o; o >>= 1) {
                sq += __shfl_xor_sync(FULLM, sq, o);
                dt += __shfl_xor_sync(FULLM, dt, o);
            }
            acc += dt / fmaxf(sqrtf(sq), 1e-8f);
        }
        if (lane == 0) s_sim[w] = acc;
        __syncthreads();
        if (tid == 0) {
            float t = 0.f;
            #pragma unroll
            for (int i = 0; i < 8; ++i) t += s_sim[i];
            g_flag[b]  = (t > 0.f) ? 1 : 0;
            g_pdone[b] = 0;              // reset for next replay
        }
        return;
    }

    // ------------------- copy body (R16-exact) -------------------
    const float4* __restrict__ src4 = (const float4*)logits;
    float4*       __restrict__ dst4 = (float4*)out;
    int base = (blk - NPOOL) * CTA_F4;

    #pragma unroll
    for (int it = 0; it < 4; ++it) {
        int b0 = base + it * (256 * C1B) + tid;
        float4 r[C1B];
        #pragma unroll
        for (int k = 0; k < C1B; ++k) {
            int ix = b0 + k * 256;
            r[k] = (ix < TOT_F4) ? __ldcs(&src4[ix])
                                 : make_float4(0.f, 0.f, 0.f, 0.f);
        }
        #pragma unroll
        for (int k = 0; k < C1B; ++k) {
            int ix = b0 + k * 256;
            if (ix < TOT_F4) __stcs(&dst4[ix], r[k]);
        }
        #pragma unroll
        for (int k = 0; k < C1B; ++k) {
            int ix = b0 + k * 256;
            if (ix < TOT_F4) {
                float mx = fmaxf(fmaxf(r[k].x, r[k].y), fmaxf(r[k].z, r[k].w));
                if (mx > THR0) {
                    float vv[4] = {r[k].x, r[k].y, r[k].z, r[k].w};
                    #pragma unroll
                    for (int c = 0; c < 4; ++c) {
                        if (vv[c] > THR0) {
                            int g   = ix * 4 + c;
                            int row = g / ROW;
                            int col = g - row * ROW;
                            int slot = atomicAdd(&g_ccnt[row], 1);
                            if (slot < CAPC)
                                g_cand[row * CAPC + slot] = make_key(vv[c], col);
                        }
                    }
                }
            }
        }
    }
}

// =======================================================================
// K2: two-level rank-count patch, 4 warps (128 thr) per row, 2 rows/CTA
//     also re-zeroes g_ccnt for the next graph replay
// =======================================================================
__global__ __launch_bounds__(256, 8)
void patch_kernel(const float* __restrict__ logits, float* __restrict__ out) {
    __shared__ __align__(16) unsigned long long s_keys[2][CAPC];  // 3 KB
    __shared__ __align__(16) unsigned long long s_sub[2][SUBC];   // 1 KB
    __shared__ int s_c[2];
    int rloc = threadIdx.x >> 7;        // 0..1 row within block
    int t128 = threadIdx.x & 127;       // 0..127 thread within row group
    int row  = blockIdx.x * 2 + rloc;
    int b    = row >> 10;

    int fl  = g_flag[b];
    int cnt = g_ccnt[row];
    bool fast = fl && (cnt >= TOPK) && (cnt <= CAPC);

    if (t128 == 0) s_c[rloc] = 0;
    __syncthreads();                     // everyone has read cnt
    if (t128 == 0) g_ccnt[row] = 0;      // reset for next replay

    // ---- stage + hi-filter: 128 threads x up to 2 keys (coalesced) ----
    const unsigned long long KHI =
        make_key(THR_HI, 0) & 0xFFFFFFFF00000000ULL;
    unsigned long long mk[2] = {0ULL, 0ULL};
    if (fast) {
        const unsigned long long* cp = g_cand + (size_t)row * CAPC;
        #pragma unroll
        for (int j = 0; j < 2; ++j) {
            int i = t128 + j * 128;
            unsigned long long k = (i < cnt && i < CAPC) ? cp[i] : 0ULL;
            mk[j] = k;
            if (i < CAPC) s_keys[rloc][i] = k;
            if (k > KHI) {
                int slot = atomicAdd(&s_c[rloc], 1);
                if (slot < SUBC) s_sub[rloc][slot] = k;
            }
        }
    }
    __syncthreads();
    if (!fl) return;

    float* dst = out + (size_t)row * ROW;
    int c_hi = s_c[rloc];

    if (fast && c_hi >= TOPK && c_hi <= SUBC) {
        // ---- level 2: rank count over ~43 refined keys, 1 key/thread ----
        if (t128 < c_hi) {
            const unsigned long long* sb = s_sub[rloc];
            unsigned long long my = sb[t128];
            int rk = 0;
            #pragma unroll 4
            for (int i = 0; i < c_hi; ++i) rk += (sb[i] > my);
            if (rk < TOPK) {
                unsigned col = 0xFFFFFFFFu - (unsigned)my;
                if (col < ROW) dst[col] = -100.0f;
            }
        }
    } else if (fast) {
        // ---- level 1 fallback: rank count over all cnt keys (rare) ----
        const unsigned long long* sk = s_keys[rloc];
        unsigned long long m0 = mk[0], m1 = mk[1];
        int r0 = 0, r1 = 0;
        #pragma unroll 4
        for (int i = 0; i < cnt; ++i) {
            unsigned long long ki = sk[i];
            r0 += (ki > m0);
            r1 += (ki > m1);
        }
        int rk[2] = {r0, r1};
        #pragma unroll
        for (int j = 0; j < 2; ++j) {
            int i = t128 + j * 128;
            if (i < cnt && i < CAPC && rk[j] < TOPK) {
                unsigned col = 0xFFFFFFFFu - (unsigned)mk[j];
                if (col < ROW) dst[col] = -100.0f;
            }
        }
    } else {
        // ---- deterministic slow path (statistically never taken) ----
        if (t128 >= 32) return;
        int lane = t128;
        const float* srcr = logits + (size_t)row * ROW;
        unsigned long long prev = ~0ULL;
        for (int t = 0; t < TOPK; ++t) {
            unsigned long long best = 0ULL;
            for (int i = lane; i < ROW; i += 32) {
                unsigned long long key = make_key(srcr[i], i);
                if (key < prev) best = umax64(best, key);
            }
            #pragma unroll
            for (int o = 16; o; o >>= 1)
                best = umax64(best, __shfl_xor_sync(FULLM, best, o));
            prev = best;
            unsigned col = 0xFFFFFFFFu - (unsigned)best;
            if (lane == 0 && best != 0ULL && col < ROW)
                dst[col] = -100.0f;
        }
    }
}

// =======================================================================
extern "C" void kernel_launch(void* const* d_in, const int* in_sizes, int n_in,
                              void* d_out, int out_size) {
    const float* proto  = (const float*)d_in[0];  // [64, 1024]
    const float* hidden = (const float*)d_in[1];  // [4, 1024, 1024]
    const float* logits = (const float*)d_in[2];  // [4, 1, 1024, 32000]
    float* out = (float*)d_out;

    fused_main<<<NPOOL + NCOPY, 256>>>(hidden, proto, logits, out);
    patch_kernel<<<NROWS / 2, 256>>>(logits, out);
}